// round 1
// baseline (speedup 1.0000x reference)
#include <cuda_runtime.h>
#include <cstdint>

// Problem geometry (fixed by the dataset)
#define B_   32
#define HW_  (512 * 512)          // 262144 pixels per (batch, channel) plane
#define NPIX ((long long)B_ * HW_) // 8,388,608 pixels total
#define HW4  (HW_ / 4)            // float4 groups per plane = 65536
#define NPIX4 (B_ * HW4)          // 2,097,152 float4 pixel-groups

#define THREADS 256
#define NBLOCKS (NPIX4 / THREADS) // 8192 blocks, each thread handles 1 float4 group

__device__ float g_partials[NBLOCKS];

__device__ __forceinline__ float hue1(float r, float g, float b) {
    float maxc = fmaxf(r, fmaxf(g, b));
    float minc = fminf(r, fminf(g, b));
    float delta = maxc - minc;
    float safe  = (delta == 0.0f) ? 1.0f : delta;
    float inv   = 1.0f / safe;
    float h;
    if (maxc == r)      h = (g - b) * inv;
    else if (maxc == g) h = 2.0f + (b - r) * inv;
    else                h = 4.0f + (r - g) * inv;
    h = (delta == 0.0f) ? 0.0f : h * (1.0f / 6.0f);
    h = h - floorf(h);   // == h/6 mod 1.0  (matches jnp semantics)
    return h;
}

__device__ __forceinline__ float pix_loss(float hp, float ht) {
    float d = fabsf(hp - ht);
    // d<0.5 -> d ; d>0.5 -> d-0.5 ; d==0.5 -> 0 (both formulas give 0)
    return (d < 0.5f) ? d : (d - 0.5f);
}

__global__ __launch_bounds__(THREADS)
void hsv_loss_main(const float4* __restrict__ pred, const float4* __restrict__ targ) {
    int gid = blockIdx.x * THREADS + threadIdx.x;   // float4 pixel-group index
    int b   = gid / HW4;
    int p4  = gid - b * HW4;
    long long base = (long long)b * 3 * HW4 + p4;   // float4 units

    float4 pr = pred[base];
    float4 pg = pred[base + HW4];
    float4 pb = pred[base + 2 * HW4];
    float4 tr = targ[base];
    float4 tg = targ[base + HW4];
    float4 tb = targ[base + 2 * HW4];

    float acc;
    acc  = pix_loss(hue1(pr.x, pg.x, pb.x), hue1(tr.x, tg.x, tb.x));
    acc += pix_loss(hue1(pr.y, pg.y, pb.y), hue1(tr.y, tg.y, tb.y));
    acc += pix_loss(hue1(pr.z, pg.z, pb.z), hue1(tr.z, tg.z, tb.z));
    acc += pix_loss(hue1(pr.w, pg.w, pb.w), hue1(tr.w, tg.w, tb.w));

    // warp reduce
    #pragma unroll
    for (int off = 16; off > 0; off >>= 1)
        acc += __shfl_xor_sync(0xFFFFFFFFu, acc, off);

    __shared__ float smem[THREADS / 32];
    int lane = threadIdx.x & 31;
    int wid  = threadIdx.x >> 5;
    if (lane == 0) smem[wid] = acc;
    __syncthreads();
    if (wid == 0) {
        float v = (lane < THREADS / 32) ? smem[lane] : 0.0f;
        #pragma unroll
        for (int off = 4; off > 0; off >>= 1)
            v += __shfl_xor_sync(0xFFFFFFFFu, v, off);
        if (lane == 0) g_partials[blockIdx.x] = v;
    }
}

__global__ __launch_bounds__(THREADS)
void hsv_loss_finish(float* __restrict__ out) {
    double acc = 0.0;
    for (int i = threadIdx.x; i < NBLOCKS; i += THREADS)
        acc += (double)g_partials[i];

    // warp reduce in double via shfl on 64-bit
    #pragma unroll
    for (int off = 16; off > 0; off >>= 1)
        acc += __shfl_xor_sync(0xFFFFFFFFu, acc, off);

    __shared__ double smem[THREADS / 32];
    int lane = threadIdx.x & 31;
    int wid  = threadIdx.x >> 5;
    if (lane == 0) smem[wid] = acc;
    __syncthreads();
    if (wid == 0) {
        double v = (lane < THREADS / 32) ? smem[lane] : 0.0;
        #pragma unroll
        for (int off = 4; off > 0; off >>= 1)
            v += __shfl_xor_sync(0xFFFFFFFFu, v, off);
        if (lane == 0) out[0] = (float)(v / (double)NPIX);
    }
}

extern "C" void kernel_launch(void* const* d_in, const int* in_sizes, int n_in,
                              void* d_out, int out_size) {
    const float4* pred = (const float4*)d_in[0];
    const float4* targ = (const float4*)d_in[1];
    float* out = (float*)d_out;

    hsv_loss_main<<<NBLOCKS, THREADS>>>(pred, targ);
    hsv_loss_finish<<<1, THREADS>>>(out);
}

// round 2
// speedup vs baseline: 1.0308x; 1.0308x over previous
#include <cuda_runtime.h>
#include <cstdint>

// Geometry (fixed by dataset): B=32, C=3, H=W=512
#define HW4_SHIFT 16
#define HW4       (1 << HW4_SHIFT)            // 65536 float4-groups per plane
#define NPIX      (32LL * 512 * 512)          // 8,388,608 pixels
#define NGROUPS   (32 * HW4)                  // 2,097,152 float4 pixel-groups

#define THREADS   256
#define NBLOCKS   2048
#define ITERS     4                           // NBLOCKS*THREADS*ITERS == NGROUPS

__device__ float        g_partials[NBLOCKS];
__device__ unsigned int g_ticket;             // zero-init, reset by last block

__device__ __forceinline__ float hue1(float r, float g, float b) {
    float maxc = fmaxf(r, fmaxf(g, b));
    float minc = fminf(r, fminf(g, b));
    float delta = maxc - minc;
    float inv   = 1.0f / ((delta == 0.0f) ? 1.0f : delta);
    float h;
    if (maxc == r)      h = (g - b) * inv;
    else if (maxc == g) h = 2.0f + (b - r) * inv;
    else                h = 4.0f + (r - g) * inv;
    h = (delta == 0.0f) ? 0.0f : h * (1.0f / 6.0f);
    return h - floorf(h);                     // h/6 mod 1.0 (jnp semantics)
}

__device__ __forceinline__ float pix_loss(float hp, float ht) {
    float d = fabsf(hp - ht);
    return (d < 0.5f) ? d : (d - 0.5f);       // d==0.5 contributes 0 either way
}

__global__ __launch_bounds__(THREADS)
void hsv_loss_fused(const float4* __restrict__ pred,
                    const float4* __restrict__ targ,
                    float* __restrict__ out) {
    float acc = 0.0f;

    #pragma unroll
    for (int k = 0; k < ITERS; k++) {
        int gid = (k * NBLOCKS + blockIdx.x) * THREADS + threadIdx.x;
        int b   = gid >> HW4_SHIFT;
        int p4  = gid & (HW4 - 1);
        long long base = ((long long)b * 3) * HW4 + p4;

        float4 pr = pred[base];
        float4 pg = pred[base + HW4];
        float4 pb = pred[base + 2 * HW4];
        float4 tr = targ[base];
        float4 tg = targ[base + HW4];
        float4 tb = targ[base + 2 * HW4];

        acc += pix_loss(hue1(pr.x, pg.x, pb.x), hue1(tr.x, tg.x, tb.x));
        acc += pix_loss(hue1(pr.y, pg.y, pb.y), hue1(tr.y, tg.y, tb.y));
        acc += pix_loss(hue1(pr.z, pg.z, pb.z), hue1(tr.z, tg.z, tb.z));
        acc += pix_loss(hue1(pr.w, pg.w, pb.w), hue1(tr.w, tg.w, tb.w));
    }

    // ---- block reduce ----
    #pragma unroll
    for (int off = 16; off > 0; off >>= 1)
        acc += __shfl_xor_sync(0xFFFFFFFFu, acc, off);

    __shared__ float swarp[THREADS / 32];
    int lane = threadIdx.x & 31;
    int wid  = threadIdx.x >> 5;
    if (lane == 0) swarp[wid] = acc;
    __syncthreads();

    __shared__ bool isLast;
    if (threadIdx.x == 0) {
        float v = 0.0f;
        #pragma unroll
        for (int w = 0; w < THREADS / 32; w++) v += swarp[w];
        g_partials[blockIdx.x] = v;
        __threadfence();
        unsigned int t = atomicAdd(&g_ticket, 1u);
        isLast = (t == NBLOCKS - 1);
    }
    __syncthreads();

    // ---- last block finishes the reduction (deterministic order) ----
    if (isLast) {
        double dacc = 0.0;
        #pragma unroll
        for (int k = 0; k < NBLOCKS / THREADS; k++)
            dacc += (double)g_partials[k * THREADS + threadIdx.x];

        #pragma unroll
        for (int off = 16; off > 0; off >>= 1)
            dacc += __shfl_xor_sync(0xFFFFFFFFu, dacc, off);

        __shared__ double sd[THREADS / 32];
        if (lane == 0) sd[wid] = dacc;
        __syncthreads();
        if (threadIdx.x == 0) {
            double v = 0.0;
            #pragma unroll
            for (int w = 0; w < THREADS / 32; w++) v += sd[w];
            out[0] = (float)(v / (double)NPIX);
            g_ticket = 0;                     // reset for next graph replay
        }
    }
}

extern "C" void kernel_launch(void* const* d_in, const int* in_sizes, int n_in,
                              void* d_out, int out_size) {
    const float4* pred = (const float4*)d_in[0];
    const float4* targ = (const float4*)d_in[1];
    float* out = (float*)d_out;
    hsv_loss_fused<<<NBLOCKS, THREADS>>>(pred, targ, out);
}